// round 11
// baseline (speedup 1.0000x reference)
#include <cuda_runtime.h>
#include <cuda_bf16.h>
#include <cstdint>

// ---------------- problem constants ----------------
#define B_SZ     2048
#define D_SZ     128
#define C_SZ     64
#define T_STEPS  300
#define HU       100
#define ROWS_TOTAL (B_SZ * T_STEPS)       // 614400
#define TILE_M   256
#define N_TILES  (ROWS_TOTAL / TILE_M)    // 2400
#define GRID     148
#define NTH      512

#define KP      112                        // padded hidden; col/row 100 = bias lane
#define BIAS_K  100
#define A_LD    120
#define W23_LD  120
#define W4_LD   136
#define W2_OFF  0
#define W3_OFF  (KP * W23_LD)
#define W4_OFF  (2 * KP * W23_LD)
#define W_TOTAL (2 * KP * W23_LD + KP * W4_LD)            // 42112 b16
#define SMEM_MAIN (2 * TILE_M * A_LD * 2 + W_TOTAL * 2)   // 207104 B

// ---------------- device globals ----------------
__device__ __align__(16) __nv_bfloat16 g_Pb[B_SZ * KP];
__device__ __align__(16) __nv_bfloat16 g_Qb[B_SZ * KP];
__device__ float g_F[B_SZ];

// ---------------- mma helpers ----------------
__device__ __forceinline__ uint32_t smem_u32(const void* p) {
    return (uint32_t)__cvta_generic_to_shared(p);
}
__device__ __forceinline__ void ldm_x4(uint32_t addr, uint32_t& r0, uint32_t& r1,
                                       uint32_t& r2, uint32_t& r3) {
    asm volatile("ldmatrix.sync.aligned.m8n8.x4.shared.b16 {%0,%1,%2,%3}, [%4];"
                 : "=r"(r0), "=r"(r1), "=r"(r2), "=r"(r3) : "r"(addr));
}
__device__ __forceinline__ void ldm_x4_t(uint32_t addr, uint32_t& r0, uint32_t& r1,
                                         uint32_t& r2, uint32_t& r3) {
    asm volatile("ldmatrix.sync.aligned.m8n8.x4.trans.shared.b16 {%0,%1,%2,%3}, [%4];"
                 : "=r"(r0), "=r"(r1), "=r"(r2), "=r"(r3) : "r"(addr));
}
__device__ __forceinline__ void mma_bf16(float c[4], uint32_t a0, uint32_t a1, uint32_t a2,
                                         uint32_t a3, uint32_t b0, uint32_t b1) {
    asm volatile(
        "mma.sync.aligned.m16n8k16.row.col.f32.bf16.bf16.f32 "
        "{%0,%1,%2,%3},{%4,%5,%6,%7},{%8,%9},{%0,%1,%2,%3};"
        : "+f"(c[0]), "+f"(c[1]), "+f"(c[2]), "+f"(c[3])
        : "r"(a0), "r"(a1), "r"(a2), "r"(a3), "r"(b0), "r"(b1));
}
__device__ __forceinline__ void barpair(int mw) {
    asm volatile("bar.sync %0, 64;" :: "r"(mw + 1) : "memory");
}

// Asymmetric-width GEMM: NT n-tiles (8 cols each) starting at column colbase.
template<int NT, int BLD>
__device__ __forceinline__ void gemm_nt(const uint16_t* aS, const uint16_t* wS,
                                        int mw, int colbase, int lane,
                                        float acc[2][8][4])
{
    #pragma unroll
    for (int mt = 0; mt < 2; mt++)
        #pragma unroll
        for (int nt = 0; nt < NT; nt++)
            #pragma unroll
            for (int i = 0; i < 4; i++) acc[mt][nt][i] = 0.f;

    int l16 = lane & 15, lh = lane >> 4;
    #pragma unroll
    for (int kk = 0; kk < 7; kk++) {
        int ks = kk * 16;
        uint32_t a[2][4];
        #pragma unroll
        for (int mt = 0; mt < 2; mt++) {
            const uint16_t* p = aS + (mw * 32 + mt * 16 + l16) * A_LD + ks + 8 * lh;
            ldm_x4(smem_u32(p), a[mt][0], a[mt][1], a[mt][2], a[mt][3]);
        }
        uint32_t b[8][2];
        #pragma unroll
        for (int np = 0; np < (NT + 1) / 2; np++) {
            const uint16_t* p = wS + (ks + l16) * BLD + colbase + np * 16 + 8 * lh;
            uint32_t r0, r1, r2, r3;
            ldm_x4_t(smem_u32(p), r0, r1, r2, r3);
            b[np * 2][0] = r0;     b[np * 2][1] = r1;
            b[np * 2 + 1][0] = r2; b[np * 2 + 1][1] = r3;
        }
        #pragma unroll
        for (int mt = 0; mt < 2; mt++)
            #pragma unroll
            for (int nt = 0; nt < NT; nt++)
                mma_bf16(acc[mt][nt], a[mt][0], a[mt][1], a[mt][2], a[mt][3],
                         b[nt][0], b[nt][1]);
    }
}

template<int NT>
__device__ __forceinline__ void epi_nt(float acc[2][8][4],
                                       uint16_t* outS, int mw, int colbase, int lane)
{
    int qrow = lane >> 2, qcol = (lane & 3) * 2;
    #pragma unroll
    for (int mt = 0; mt < 2; mt++) {
        int r = mw * 32 + mt * 16 + qrow;
        #pragma unroll
        for (int nt = 0; nt < NT; nt++) {
            int c = colbase + nt * 8 + qcol;
            float v0 = fmaxf(acc[mt][nt][0], 0.f);
            float v1 = fmaxf(acc[mt][nt][1], 0.f);
            float v2 = fmaxf(acc[mt][nt][2], 0.f);
            float v3 = fmaxf(acc[mt][nt][3], 0.f);
            __nv_bfloat162 h0 = __floats2bfloat162_rn(v0, v1);
            __nv_bfloat162 h1 = __floats2bfloat162_rn(v2, v3);
            *(uint32_t*)(outS + r * A_LD + c)       = *(uint32_t*)&h0;
            *(uint32_t*)(outS + (r + 8) * A_LD + c) = *(uint32_t*)&h1;
        }
    }
}

// ---------------- prep v5: 512 CTAs x 512 thr, L1||P overlap, dual accumulators ---
__global__ void __launch_bounds__(512)
prep_all(const float* __restrict__ x,
         const float* __restrict__ W1, const float* __restrict__ b1,
         const float* __restrict__ W2, const float* __restrict__ b2,
         const float* __restrict__ W3, const float* __restrict__ b3,
         const float* __restrict__ U1, const float* __restrict__ c1)
{
    __shared__ float sx[4][132];
    __shared__ float sa[4][204];
    __shared__ float sb[4][204];
    __shared__ float sh[4][68];
    int tid = threadIdx.x;
    int m0 = blockIdx.x * 4;

    if (tid < 512) {
        int i = tid;                           // 4*128 = 512 exactly
        sx[i >> 7][i & 127] = __ldg(x + m0 * D_SZ + i);
    }
    if (tid < 4) g_F[m0 + tid] = 0.f;
    __syncthreads();

    // ---- phase A: L1 (tid<200) || P (256<=tid<356) || P-pad (356<=tid<368) ----
    if (tid < 200) {
        int n = tid;
        float accA[4] = {}, accB[4] = {};
        #pragma unroll 4
        for (int k = 0; k < 128; k += 4) {
            float w0 = __ldg(W1 + k * 200 + n);
            float w1 = __ldg(W1 + (k + 1) * 200 + n);
            float w2 = __ldg(W1 + (k + 2) * 200 + n);
            float w3 = __ldg(W1 + (k + 3) * 200 + n);
            #pragma unroll
            for (int r = 0; r < 4; r++) {
                accA[r] = fmaf(sx[r][k], w0, accA[r]);
                accB[r] = fmaf(sx[r][k + 1], w1, accB[r]);
                accA[r] = fmaf(sx[r][k + 2], w2, accA[r]);
                accB[r] = fmaf(sx[r][k + 3], w3, accB[r]);
            }
        }
        float bb = __ldg(b1 + n);
        #pragma unroll
        for (int r = 0; r < 4; r++) sa[r][n] = fmaxf(accA[r] + accB[r] + bb, 0.f);
    } else if (tid >= 256 && tid < 356) {
        int n = tid - 256;
        float accA[4] = {}, accB[4] = {};
        #pragma unroll 4
        for (int k = 0; k < 128; k += 4) {
            float w0 = __ldg(U1 + k * HU + n);
            float w1 = __ldg(U1 + (k + 1) * HU + n);
            float w2 = __ldg(U1 + (k + 2) * HU + n);
            float w3 = __ldg(U1 + (k + 3) * HU + n);
            #pragma unroll
            for (int r = 0; r < 4; r++) {
                accA[r] = fmaf(sx[r][k], w0, accA[r]);
                accB[r] = fmaf(sx[r][k + 1], w1, accB[r]);
                accA[r] = fmaf(sx[r][k + 2], w2, accA[r]);
                accB[r] = fmaf(sx[r][k + 3], w3, accB[r]);
            }
        }
        #pragma unroll
        for (int r = 0; r < 4; r++)
            g_Pb[(m0 + r) * KP + n] = __float2bfloat16(accA[r] + accB[r]);
    } else if (tid >= 356 && tid < 368) {
        int c = tid - 356 + 100;               // 100..111
        #pragma unroll
        for (int r = 0; r < 4; r++)
            g_Pb[(m0 + r) * KP + c] = __float2bfloat16(0.f);
    }
    __syncthreads();

    // ---- phase B: L2 (tid<200), K=200 ----
    if (tid < 200) {
        int n = tid;
        float accA[4] = {}, accB[4] = {};
        #pragma unroll 4
        for (int k = 0; k < 200; k += 4) {
            float w0 = __ldg(W2 + k * 200 + n);
            float w1 = __ldg(W2 + (k + 1) * 200 + n);
            float w2 = __ldg(W2 + (k + 2) * 200 + n);
            float w3 = __ldg(W2 + (k + 3) * 200 + n);
            #pragma unroll
            for (int r = 0; r < 4; r++) {
                accA[r] = fmaf(sa[r][k], w0, accA[r]);
                accB[r] = fmaf(sa[r][k + 1], w1, accB[r]);
                accA[r] = fmaf(sa[r][k + 2], w2, accA[r]);
                accB[r] = fmaf(sa[r][k + 3], w3, accB[r]);
            }
        }
        float bb = __ldg(b2 + n);
        #pragma unroll
        for (int r = 0; r < 4; r++) sb[r][n] = fmaxf(accA[r] + accB[r] + bb, 0.f);
    }
    __syncthreads();

    // ---- phase C: L3 (tid<256), 64 cols x 4 rows, 1 output/thread, K=200 ----
    if (tid < 256) {
        int n = tid & 63, r = tid >> 6;
        float a0 = 0.f, a1 = 0.f, a2 = 0.f, a3 = 0.f;
        const float* ar = sb[r];
        #pragma unroll 4
        for (int k = 0; k < 200; k += 4) {
            a0 = fmaf(ar[k],     __ldg(W3 + k * C_SZ + n), a0);
            a1 = fmaf(ar[k + 1], __ldg(W3 + (k + 1) * C_SZ + n), a1);
            a2 = fmaf(ar[k + 2], __ldg(W3 + (k + 2) * C_SZ + n), a2);
            a3 = fmaf(ar[k + 3], __ldg(W3 + (k + 3) * C_SZ + n), a3);
        }
        sh[r][n] = fmaxf((a0 + a1) + (a2 + a3) + __ldg(b3 + n), 0.f);
    }
    __syncthreads();

    // ---- phase D: Q (tid<100), K=64 ; Q-pad (100..111) ----
    if (tid < 100) {
        int n = tid;
        const float* Uq = U1 + D_SZ * HU;
        float accA[4] = {}, accB[4] = {};
        #pragma unroll 4
        for (int k = 0; k < 64; k += 4) {
            float w0 = __ldg(Uq + k * HU + n);
            float w1 = __ldg(Uq + (k + 1) * HU + n);
            float w2 = __ldg(Uq + (k + 2) * HU + n);
            float w3 = __ldg(Uq + (k + 3) * HU + n);
            #pragma unroll
            for (int r = 0; r < 4; r++) {
                accA[r] = fmaf(sh[r][k], w0, accA[r]);
                accB[r] = fmaf(sh[r][k + 1], w1, accB[r]);
                accA[r] = fmaf(sh[r][k + 2], w2, accA[r]);
                accB[r] = fmaf(sh[r][k + 3], w3, accB[r]);
            }
        }
        float cc = __ldg(c1 + n);
        #pragma unroll
        for (int r = 0; r < 4; r++)
            g_Qb[(m0 + r) * KP + n] = __float2bfloat16(accA[r] + accB[r] + cc);
    } else if (tid < 112) {
        float v = (tid == BIAS_K) ? 1.0f : 0.0f;
        #pragma unroll
        for (int r = 0; r < 4; r++)
            g_Qb[(m0 + r) * KP + tid] = __float2bfloat16(v);
    }
}

// ---------------- main: persistent bf16 mma kernel (+ next-tile P/Q prefetch) ----
__global__ void __launch_bounds__(NTH, 1)
umnn_main(const float* __restrict__ x,
          const float* __restrict__ U2, const float* __restrict__ c2,
          const float* __restrict__ U3, const float* __restrict__ c3,
          const float* __restrict__ U4, const float* __restrict__ c4)
{
    extern __shared__ __align__(16) uint16_t sm[];
    uint16_t* As1 = sm;
    uint16_t* As2 = sm + TILE_M * A_LD;
    uint16_t* Wsm = sm + 2 * TILE_M * A_LD;

    int tid = threadIdx.x;
    int lane = tid & 31, w = tid >> 5;
    int mw = w & 7, nw = w >> 3;

    // zero activation buffers (unwritten cols stay 0 forever; avoids NaN*0)
    for (int i = tid; i < 2 * TILE_M * A_LD; i += NTH) sm[i] = 0;

    // pack weights with bias folded into k-row BIAS_K
    for (int i = tid; i < KP * W23_LD; i += NTH) {
        int k = i / W23_LD, n = i - k * W23_LD;
        float a = 0.f, b = 0.f;
        if (k < HU && n < HU) {
            a = __ldg(U2 + k * HU + n);
            b = __ldg(U3 + k * HU + n);
        } else if (k == BIAS_K) {
            if (n < HU)            { a = __ldg(c2 + n); b = __ldg(c3 + n); }
            else if (n == BIAS_K)  { a = 1.0f;          b = 1.0f; }
        }
        __nv_bfloat16 ha = __float2bfloat16(a), hb = __float2bfloat16(b);
        Wsm[W2_OFF + i] = *(uint16_t*)&ha;
        Wsm[W3_OFF + i] = *(uint16_t*)&hb;
    }
    for (int i = tid; i < KP * W4_LD; i += NTH) {
        int k = i / W4_LD, n = i - k * W4_LD;
        float a = 0.f;
        if (k < HU && n < D_SZ)            a = __ldg(U4 + k * D_SZ + n);
        else if (k == BIAS_K && n < D_SZ)  a = __ldg(c4 + n);
        __nv_bfloat16 ha = __float2bfloat16(a);
        Wsm[W4_OFF + i] = *(uint16_t*)&ha;
    }
    __syncthreads();

    const uint16_t* W2s = Wsm + W2_OFF;
    const uint16_t* W3s = Wsm + W3_OFF;
    const uint16_t* W4s = Wsm + W4_OFF;

    int sl = nw * 32 + lane;
    int blr = sl >> 1, bhalf = sl & 1;
    int qrow = lane >> 2, qcol = (lane & 3) * 2;

    float acc[2][8][4];

    for (int tile = blockIdx.x; tile < N_TILES; tile += GRID) {
        int r0 = tile * TILE_M;
        int b0 = r0 / T_STEPS;
        int split = (b0 + 1) * T_STEPS - r0;

        barpair(mw);

        // build A1 = bf16(relu(t*P[b] + Q[b])) (col BIAS_K -> 1)
        {
            int row = mw * 32 + blr;
            int r = r0 + row;
            int b = r / T_STEPS;
            float tv = ((float)(r - b * T_STEPS) + 0.5f) * (1.0f / T_STEPS);
            const uint4* Pp = (const uint4*)(g_Pb + b * KP + bhalf * 56);
            const uint4* Qp = (const uint4*)(g_Qb + b * KP + bhalf * 56);
            uint4* dst = (uint4*)(As1 + row * A_LD + bhalf * 56);
            #pragma unroll
            for (int j = 0; j < 7; j++) {
                uint4 pv = __ldg(Pp + j);
                uint4 qv = __ldg(Qp + j);
                uint32_t pw[4] = {pv.x, pv.y, pv.z, pv.w};
                uint32_t qw[4] = {qv.x, qv.y, qv.z, qv.w};
                uint32_t ow[4];
                #pragma unroll
                for (int u = 0; u < 4; u++) {
                    float2 p2 = __bfloat1622float2(*(__nv_bfloat162*)&pw[u]);
                    float2 q2 = __bfloat1622float2(*(__nv_bfloat162*)&qw[u]);
                    float v0 = fmaxf(fmaf(tv, p2.x, q2.x), 0.f);
                    float v1 = fmaxf(fmaf(tv, p2.y, q2.y), 0.f);
                    __nv_bfloat162 h = __floats2bfloat162_rn(v0, v1);
                    ow[u] = *(uint32_t*)&h;
                }
                dst[j] = make_uint4(ow[0], ow[1], ow[2], ow[3]);
            }

            // prefetch next tile's P/Q rows into L2 (hidden behind L2/L3/L4 MMAs)
            int ntile = tile + GRID;
            if (ntile < N_TILES) {
                int rn = ntile * TILE_M + row;
                int bn = rn / T_STEPS;
                const char* pp = (const char*)(g_Pb + bn * KP + bhalf * 56);
                const char* qp = (const char*)(g_Qb + bn * KP + bhalf * 56);
                asm volatile("prefetch.global.L2 [%0];" :: "l"(pp));
                asm volatile("prefetch.global.L2 [%0+64];" :: "l"(pp));
                asm volatile("prefetch.global.L2 [%0];" :: "l"(qp));
                asm volatile("prefetch.global.L2 [%0+64];" :: "l"(qp));
            }
        }
        barpair(mw);

        // L2 (13 n-tiles: nw0 -> 7 @0, nw1 -> 6 @56)
        if (nw == 0) {
            gemm_nt<7, W23_LD>(As1, W2s, mw, 0, lane, acc);
            epi_nt<7>(acc, As2, mw, 0, lane);
        } else {
            gemm_nt<6, W23_LD>(As1, W2s, mw, 56, lane, acc);
            epi_nt<6>(acc, As2, mw, 56, lane);
        }
        barpair(mw);

        // L3
        if (nw == 0) {
            gemm_nt<7, W23_LD>(As2, W3s, mw, 0, lane, acc);
            epi_nt<7>(acc, As1, mw, 0, lane);
        } else {
            gemm_nt<6, W23_LD>(As2, W3s, mw, 56, lane, acc);
            epi_nt<6>(acc, As1, mw, 56, lane);
        }
        barpair(mw);

        // L4 (full 16 n-tiles: 8 per warp) + quadrature dot
        gemm_nt<8, W4_LD>(As1, W4s, mw, nw * 64, lane, acc);
        {
            #pragma unroll
            for (int mt = 0; mt < 2; mt++) {
                int rA = mw * 32 + mt * 16 + qrow;
                int rB = rA + 8;
                int bA = b0 + (rA >= split);
                int bB = b0 + (rB >= split);
                const float* xA = x + bA * D_SZ;
                const float* xB = x + bB * D_SZ;
                float sA = 0.f, sB = 0.f;
                #pragma unroll
                for (int nt = 0; nt < 8; nt++) {
                    int c = nw * 64 + nt * 8 + qcol;
                    float p0 = acc[mt][nt][0], p1 = acc[mt][nt][1];
                    float p2 = acc[mt][nt][2], p3 = acc[mt][nt][3];
                    float f0 = p0 > 0.f ? p0 + 1.f : __expf(p0);
                    float f1 = p1 > 0.f ? p1 + 1.f : __expf(p1);
                    float f2 = p2 > 0.f ? p2 + 1.f : __expf(p2);
                    float f3 = p3 > 0.f ? p3 + 1.f : __expf(p3);
                    sA += f0 * __ldg(xA + c) + f1 * __ldg(xA + c + 1);
                    sB += f2 * __ldg(xB + c) + f3 * __ldg(xB + c + 1);
                }
                sA += __shfl_xor_sync(0xffffffff, sA, 1);
                sA += __shfl_xor_sync(0xffffffff, sA, 2);
                sB += __shfl_xor_sync(0xffffffff, sB, 1);
                sB += __shfl_xor_sync(0xffffffff, sB, 2);
                if ((lane & 3) == 0) {
                    atomicAdd(&g_F[bA], sA);
                    atomicAdd(&g_F[bB], sB);
                }
            }
        }
    }
}

// ---------------- finish: sigmoid(F / T) ----------------
__global__ void finish_kernel(float* __restrict__ out)
{
    int i = blockIdx.x * blockDim.x + threadIdx.x;
    if (i < B_SZ) {
        float F = g_F[i] * (1.0f / T_STEPS);
        out[i] = 1.0f / (1.0f + expf(-F));
    }
}

// ---------------- launch ----------------
extern "C" void kernel_launch(void* const* d_in, const int* in_sizes, int n_in,
                              void* d_out, int out_size)
{
    (void)in_sizes; (void)n_in; (void)out_size;
    const float* x  = (const float*)d_in[0];
    const float* W1 = (const float*)d_in[1];
    const float* b1 = (const float*)d_in[2];
    const float* W2 = (const float*)d_in[3];
    const float* b2 = (const float*)d_in[4];
    const float* W3 = (const float*)d_in[5];
    const float* b3 = (const float*)d_in[6];
    const float* U1 = (const float*)d_in[7];
    const float* c1 = (const float*)d_in[8];
    const float* U2 = (const float*)d_in[9];
    const float* c2 = (const float*)d_in[10];
    const float* U3 = (const float*)d_in[11];
    const float* c3 = (const float*)d_in[12];
    const float* U4 = (const float*)d_in[13];
    const float* c4 = (const float*)d_in[14];
    float* out = (float*)d_out;

    cudaFuncSetAttribute(umnn_main, cudaFuncAttributeMaxDynamicSharedMemorySize, SMEM_MAIN);

    // 1) prep v5: 512 CTAs x 512 thr, L1||P overlap, dual accumulators
    prep_all<<<512, 512>>>(x, W1, b1, W2, b2, W3, b3, U1, c1);
    // 2) persistent bf16 mma main kernel (+ P/Q L2 prefetch)
    umnn_main<<<GRID, NTH, SMEM_MAIN>>>(x, U2, c2, U3, c3, U4, c4);
    // 3) out = sigmoid(F / 300)
    finish_kernel<<<(B_SZ + 255) / 256, 256>>>(out);
}